// round 9
// baseline (speedup 1.0000x reference)
#include <cuda_runtime.h>
#include <cuda_fp16.h>
#include <cstdint>

// ---------------- problem constants ----------------
#define IN_F   4096
#define OUT_F  4096
#define M_TOT  8192
#define BK     128          // k per iteration (= one scale group, 256B A rows)
#define KITERS (IN_F / BK)  // 32
#define BM     128
#define BN     64
#define NTH    128          // 4 warps: 2 (M) x 2 (N), 64x32 warp tiles

// ---------------- static device scratch ----------------
// inverted transposed sign bits: bit=1 -> weight NEGATIVE; [kword][o]
__device__ uint32_t g_packT[(size_t)(IN_F / 32) * OUT_F];   // 2 MB
__device__ __half   g_xh[(size_t)M_TOT * IN_F];             // 64 MB
// per (kgroup, o): half2(s, s) as uint32
__device__ uint32_t g_ppT[(size_t)(IN_F / 128) * OUT_F];    // 512 KB

// ---------------- SMEM: A-only ring, 3 stages ----------------
#define STAGE_BYTES 32768    // 128 rows x 256B, xor-8 chunk swizzle
#define STAGES      3
#define SM_TOTAL    (STAGES * STAGE_BYTES)   // 98304

// ---------------- helpers ----------------
static __device__ __forceinline__ uint32_t smem_u32(const void* p) {
    uint32_t a;
    asm("{ .reg .u64 t; cvta.to.shared.u64 t, %1; cvt.u32.u64 %0, t; }"
        : "=r"(a) : "l"(p));
    return a;
}

#define CP_ASYNC16(dst, src) \
    asm volatile("cp.async.cg.shared.global [%0], [%1], 16;" :: "r"(dst), "l"(src))
#define CP_COMMIT()  asm volatile("cp.async.commit_group;" ::: "memory")
#define CP_WAIT1()   asm volatile("cp.async.wait_group 1;" ::: "memory")
#define CP_WAIT0()   asm volatile("cp.async.wait_group 0;" ::: "memory")

static __device__ __forceinline__ void ldsm_x4(uint32_t* r, uint32_t addr) {
    asm volatile("ldmatrix.sync.aligned.m8n8.x4.shared.b16 {%0,%1,%2,%3}, [%4];"
                 : "=r"(r[0]), "=r"(r[1]), "=r"(r[2]), "=r"(r[3]) : "r"(addr));
}

static __device__ __forceinline__ void mma_fp16(float* d, const uint32_t* a,
                                                uint32_t b0, uint32_t b1) {
    asm volatile(
        "mma.sync.aligned.m16n8k16.row.col.f32.f16.f16.f32 "
        "{%0,%1,%2,%3}, {%4,%5,%6,%7}, {%8,%9}, {%0,%1,%2,%3};"
        : "+f"(d[0]), "+f"(d[1]), "+f"(d[2]), "+f"(d[3])
        : "r"(a[0]), "r"(a[1]), "r"(a[2]), "r"(a[3]), "r"(b0), "r"(b1));
}

// ============================================================
// Kernel 0: convert X fp32 -> fp16 (RN)
// ============================================================
__global__ void __launch_bounds__(256)
convert_x_kernel(const float4* __restrict__ x4) {
    size_t i = (size_t)blockIdx.x * 256 + threadIdx.x;
    float4 a = x4[2 * i];
    float4 b = x4[2 * i + 1];
    __half2 h0 = __floats2half2_rn(a.x, a.y);
    __half2 h1 = __floats2half2_rn(a.z, a.w);
    __half2 h2 = __floats2half2_rn(b.x, b.y);
    __half2 h3 = __floats2half2_rn(b.z, b.w);
    uint4 q;
    q.x = *reinterpret_cast<uint32_t*>(&h0);
    q.y = *reinterpret_cast<uint32_t*>(&h1);
    q.z = *reinterpret_cast<uint32_t*>(&h2);
    q.w = *reinterpret_cast<uint32_t*>(&h3);
    *reinterpret_cast<uint4*>(&g_xh[i * 8]) = q;
}

// ============================================================
// Kernel 1: pack INVERTED sign bits, transposed: packT[kw*4096 + o]
// ============================================================
__global__ void __launch_bounds__(256)
pack_signs_kernel(const float* __restrict__ sw) {
    uint32_t W = blockIdx.x * 8u + (threadIdx.x >> 5);
    uint32_t lane = threadIdx.x & 31;
    uint32_t o = W >> 7;
    uint32_t kw = W & 127;
    float v = sw[(size_t)o * IN_F + kw * 32 + lane];
    uint32_t m = __ballot_sync(0xFFFFFFFFu, v < 0.0f);
    if (lane == 0) g_packT[(size_t)kw * OUT_F + o] = m;
}

// ============================================================
// Kernel 1b: scales -> half2(s,s) words, transposed: ppT[kg*4096 + o]
// ============================================================
__global__ void __launch_bounds__(256)
pack_scales_kernel(const float* __restrict__ scales) {
    int idx = blockIdx.x * 256 + threadIdx.x;
    int kg = idx >> 12;
    int o = idx & 4095;
    __half h = __float2half_rn(scales[(size_t)o * (IN_F / 128) + kg]);
    __half2 hh = __half2half2(h);
    g_ppT[(size_t)kg * OUT_F + o] = *reinterpret_cast<uint32_t*>(&hh);
}

// ============================================================
// Kernel 2: fp16 mma.sync GEMM, CTA 128x64xBK128, 4 warps 64x32
// A: 3-stage cp.async ring prefetched 2 iters ahead.
// Signs/scales: LDG from L2 into regs, prefetched 1 iter ahead.
// ============================================================
__global__ void __launch_bounds__(NTH, 2)
bitlinear_mma_kernel(float* __restrict__ out) {
    extern __shared__ char smem[];
    const uint32_t smem_base = smem_u32(smem);

    const int tid = threadIdx.x;
    const int wid = tid >> 5;
    const int lane = tid & 31;
    const int g = lane >> 2;
    const int t = lane & 3;
    const int wm_i = wid >> 1;           // 0..1
    const int wn_i = wid & 1;            // 0..1

    const int mt = blockIdx.x >> 6;      // consecutive CTAs share the A tile
    const int nt = blockIdx.x & 63;
    const int m0 = mt * BM;
    const int o0 = nt * BN;

    // ---- A cp.async addressing: 2048 chunks, 16 per thread ----
    const int arow = tid >> 4;           // 0..7, covers rows arow + 8j
    const int ac = tid & 15;             // chunk 0..15
    const __half* xsrc0 = g_xh + (size_t)(m0 + arow) * IN_F + ac * 8;
    const uint32_t adst0 = (uint32_t)(arow * 256 + ((ac ^ arow) << 4));

    // ---- sign/scale LDG column indices for this lane's 4 cols ----
    int cnj[4];
    #pragma unroll
    for (int nj = 0; nj < 4; ++nj)
        cnj[nj] = o0 + wn_i * 32 + g + 8 * nj;

    float acc[4][4][4];
    #pragma unroll
    for (int mi = 0; mi < 4; ++mi)
        #pragma unroll
        for (int nj = 0; nj < 4; ++nj)
            #pragma unroll
            for (int r = 0; r < 4; ++r) acc[mi][nj][r] = 0.0f;

    // ---- ldmatrix A lane components ----
    const int a_row_l = wm_i * 64 + (lane & 15);
    const int a_hl = lane >> 4;          // 0/1 -> chunk 2ks + hl
    const int t2 = 2 * t;

    auto fill = [&](int it, int s) {
        const uint32_t sb = smem_base + (uint32_t)(s * STAGE_BYTES);
        const __half* src = xsrc0 + (size_t)it * BK;
        #pragma unroll
        for (int j = 0; j < 16; ++j)
            CP_ASYNC16(sb + adst0 + (uint32_t)(j * 2048),
                       (const char*)(src + (size_t)j * 8 * IN_F));
    };

    // ---- prologue: A stages 0,1 in flight; signs/scales(0) via LDG ----
    fill(0, 0); CP_COMMIT();
    fill(1, 1); CP_COMMIT();

    uint32_t wc[4][4], ppc[4];
    #pragma unroll
    for (int kw = 0; kw < 4; ++kw)
        #pragma unroll
        for (int nj = 0; nj < 4; ++nj)
            wc[kw][nj] = __ldg(&g_packT[(size_t)kw * OUT_F + cnj[nj]]);
    #pragma unroll
    for (int nj = 0; nj < 4; ++nj)
        ppc[nj] = __ldg(&g_ppT[cnj[nj]]);

    #pragma unroll 1
    for (int it = 0; it < KITERS; ++it) {
        // ensure A(it) resident (committed 2 iterations ago -> slack)
        if (it < KITERS - 1) { CP_WAIT1(); } else { CP_WAIT0(); }
        __syncthreads();

        // refill the stage consumed at it-1 with A(it+2)
        if (it + 2 < KITERS) {
            fill(it + 2, (it + 2) % 3);
            CP_COMMIT();
        }

        // prefetch signs/scales(it+1) from L2 into regs
        uint32_t wn_[4][4], ppn_[4];
        if (it + 1 < KITERS) {
            #pragma unroll
            for (int kw = 0; kw < 4; ++kw)
                #pragma unroll
                for (int nj = 0; nj < 4; ++nj)
                    wn_[kw][nj] = __ldg(&g_packT[(size_t)(4 * (it + 1) + kw) * OUT_F + cnj[nj]]);
            #pragma unroll
            for (int nj = 0; nj < 4; ++nj)
                ppn_[nj] = __ldg(&g_ppT[(size_t)(it + 1) * OUT_F + cnj[nj]]);
        }

        // ---- compute from stage it%3, A frags double-buffered ----
        const uint32_t abase = smem_base + (uint32_t)((it % 3) * STAGE_BYTES);
        uint32_t af[2][4][4];
        #pragma unroll
        for (int mi = 0; mi < 4; ++mi) {
            const int r = a_row_l + mi * 16;
            const int ch = a_hl ^ (r & 7);
            ldsm_x4(af[0][mi], abase + (uint32_t)(r * 256 + (ch << 4)));
        }

        #pragma unroll
        for (int ks = 0; ks < 8; ++ks) {
            const int cur = ks & 1;
            if (ks < 7) {
                #pragma unroll
                for (int mi = 0; mi < 4; ++mi) {
                    const int r = a_row_l + mi * 16;
                    const int ch = (2 * (ks + 1) + a_hl) ^ (r & 7);
                    ldsm_x4(af[cur ^ 1][mi], abase + (uint32_t)(r * 256 + (ch << 4)));
                }
            }
            const int kw = ks >> 1;
            const int sh = t2 + ((ks & 1) << 4);
            #pragma unroll
            for (int nj = 0; nj < 4; ++nj) {
                uint32_t v = wc[kw][nj] >> sh;
                uint32_t b0 = ppc[nj] ^ (((v << 15) & 0x8000u) | ((v << 30) & 0x80000000u));
                uint32_t b1 = ppc[nj] ^ (((v << 7) & 0x8000u) | ((v << 22) & 0x80000000u));
                #pragma unroll
                for (int mi = 0; mi < 4; ++mi)
                    mma_fp16(acc[mi][nj], af[cur][mi], b0, b1);
            }
        }

        // rotate sign/scale registers
        if (it + 1 < KITERS) {
            #pragma unroll
            for (int kw = 0; kw < 4; ++kw)
                #pragma unroll
                for (int nj = 0; nj < 4; ++nj)
                    wc[kw][nj] = wn_[kw][nj];
            #pragma unroll
            for (int nj = 0; nj < 4; ++nj)
                ppc[nj] = ppn_[nj];
        }
    }

    // ---- epilogue: direct STG.64 ----
    #pragma unroll
    for (int mi = 0; mi < 4; ++mi) {
        const int row = m0 + wm_i * 64 + mi * 16 + g;
        #pragma unroll
        for (int nj = 0; nj < 4; ++nj) {
            const int col = o0 + wn_i * 32 + nj * 8 + 2 * t;
            float2 v0 = make_float2(acc[mi][nj][0], acc[mi][nj][1]);
            float2 v1 = make_float2(acc[mi][nj][2], acc[mi][nj][3]);
            *reinterpret_cast<float2*>(out + (size_t)row * OUT_F + col) = v0;
            *reinterpret_cast<float2*>(out + (size_t)(row + 8) * OUT_F + col) = v1;
        }
    }
}

// ============================================================
// launch
// ============================================================
extern "C" void kernel_launch(void* const* d_in, const int* in_sizes, int n_in,
                              void* d_out, int out_size) {
    const float* x      = (const float*)d_in[0];
    const float* sw     = (const float*)d_in[1];
    const float* scales = (const float*)d_in[2];
    float* out = (float*)d_out;

    cudaFuncSetAttribute(bitlinear_mma_kernel,
                         cudaFuncAttributeMaxDynamicSharedMemorySize, SM_TOTAL);

    convert_x_kernel<<<(M_TOT * (size_t)IN_F) / (8 * 256), 256>>>((const float4*)x);
    pack_signs_kernel<<<65536, 256>>>(sw);
    pack_scales_kernel<<<512, 256>>>(scales);

    // 64 M-tiles x 64 N-tiles; consecutive CTAs share the M tile (A reuse in L2)
    bitlinear_mma_kernel<<<(M_TOT / BM) * (OUT_F / BN), NTH, SM_TOTAL>>>(out);
}

// round 10
// speedup vs baseline: 1.1416x; 1.1416x over previous
#include <cuda_runtime.h>
#include <cuda_fp16.h>
#include <cstdint>

// ---------------- problem constants ----------------
#define IN_F   4096
#define OUT_F  4096
#define M_TOT  8192
#define BK     128          // k per iteration (= one scale group, 256B A rows)
#define KITERS (IN_F / BK)  // 32
#define BM     128
#define BN     128
#define NTH    128          // 4 warps: 2 (M) x 2 (N), 64x64 warp tiles

// ---------------- static device scratch ----------------
// inverted transposed sign bits: bit=1 -> weight NEGATIVE; [kword][o]
__device__ uint32_t g_packT[(size_t)(IN_F / 32) * OUT_F];   // 2 MB
__device__ __half   g_xh[(size_t)M_TOT * IN_F];             // 64 MB
// per (kgroup, o): half2(s, s) as uint32
__device__ uint32_t g_ppT[(size_t)(IN_F / 128) * OUT_F];    // 512 KB

// ---------------- SMEM layout ----------------
// A ring: 3 stages x 32768 (128 rows x 256B, xor-8 chunk swizzle)
// WS ring: 3 stages x 2560 (W: 4 kwords x 128 cols x 4B = 2048; S: 128 x 4B = 512)
#define A_STAGE   32768
#define WS_BASE   (3 * A_STAGE)        // 98304
#define WS_STAGE  2560
#define SM_TOTAL  (WS_BASE + 3 * WS_STAGE)   // 105984

// ---------------- helpers ----------------
static __device__ __forceinline__ uint32_t smem_u32(const void* p) {
    uint32_t a;
    asm("{ .reg .u64 t; cvta.to.shared.u64 t, %1; cvt.u32.u64 %0, t; }"
        : "=r"(a) : "l"(p));
    return a;
}

#define CP_ASYNC16(dst, src) \
    asm volatile("cp.async.cg.shared.global [%0], [%1], 16;" :: "r"(dst), "l"(src))
#define CP_COMMIT()  asm volatile("cp.async.commit_group;" ::: "memory")
#define CP_WAIT1()   asm volatile("cp.async.wait_group 1;" ::: "memory")
#define CP_WAIT0()   asm volatile("cp.async.wait_group 0;" ::: "memory")

static __device__ __forceinline__ void ldsm_x4(uint32_t* r, uint32_t addr) {
    asm volatile("ldmatrix.sync.aligned.m8n8.x4.shared.b16 {%0,%1,%2,%3}, [%4];"
                 : "=r"(r[0]), "=r"(r[1]), "=r"(r[2]), "=r"(r[3]) : "r"(addr));
}

static __device__ __forceinline__ void mma_fp16(float* d, const uint32_t* a,
                                                uint32_t b0, uint32_t b1) {
    asm volatile(
        "mma.sync.aligned.m16n8k16.row.col.f32.f16.f16.f32 "
        "{%0,%1,%2,%3}, {%4,%5,%6,%7}, {%8,%9}, {%0,%1,%2,%3};"
        : "+f"(d[0]), "+f"(d[1]), "+f"(d[2]), "+f"(d[3])
        : "r"(a[0]), "r"(a[1]), "r"(a[2]), "r"(a[3]), "r"(b0), "r"(b1));
}

// ============================================================
// Kernel 0: convert X fp32 -> fp16 (RN)
// ============================================================
__global__ void __launch_bounds__(256)
convert_x_kernel(const float4* __restrict__ x4) {
    size_t i = (size_t)blockIdx.x * 256 + threadIdx.x;
    float4 a = x4[2 * i];
    float4 b = x4[2 * i + 1];
    __half2 h0 = __floats2half2_rn(a.x, a.y);
    __half2 h1 = __floats2half2_rn(a.z, a.w);
    __half2 h2 = __floats2half2_rn(b.x, b.y);
    __half2 h3 = __floats2half2_rn(b.z, b.w);
    uint4 q;
    q.x = *reinterpret_cast<uint32_t*>(&h0);
    q.y = *reinterpret_cast<uint32_t*>(&h1);
    q.z = *reinterpret_cast<uint32_t*>(&h2);
    q.w = *reinterpret_cast<uint32_t*>(&h3);
    *reinterpret_cast<uint4*>(&g_xh[i * 8]) = q;
}

// ============================================================
// Kernel 1: pack INVERTED sign bits, transposed: packT[kw*4096 + o]
// ============================================================
__global__ void __launch_bounds__(256)
pack_signs_kernel(const float* __restrict__ sw) {
    uint32_t W = blockIdx.x * 8u + (threadIdx.x >> 5);
    uint32_t lane = threadIdx.x & 31;
    uint32_t o = W >> 7;
    uint32_t kw = W & 127;
    float v = sw[(size_t)o * IN_F + kw * 32 + lane];
    uint32_t m = __ballot_sync(0xFFFFFFFFu, v < 0.0f);
    if (lane == 0) g_packT[(size_t)kw * OUT_F + o] = m;
}

// ============================================================
// Kernel 1b: scales -> half2(s,s) words, transposed: ppT[kg*4096 + o]
// ============================================================
__global__ void __launch_bounds__(256)
pack_scales_kernel(const float* __restrict__ scales) {
    int idx = blockIdx.x * 256 + threadIdx.x;
    int kg = idx >> 12;
    int o = idx & 4095;
    __half h = __float2half_rn(scales[(size_t)o * (IN_F / 128) + kg]);
    __half2 hh = __half2half2(h);
    g_ppT[(size_t)kg * OUT_F + o] = *reinterpret_cast<uint32_t*>(&hh);
}

// ============================================================
// Kernel 2: fp16 mma.sync GEMM, CTA 128x128xBK128, 4 warps 64x64
// A: 3-stage ring, filled 2 iters ahead.
// W/S: 3-stage ring, filled 3 iters ahead; preloaded to regs 1 iter early.
// ============================================================
__global__ void __launch_bounds__(NTH, 2)
bitlinear_mma_kernel(float* __restrict__ out) {
    extern __shared__ char smem[];
    const uint32_t smem_base = smem_u32(smem);

    const int tid = threadIdx.x;
    const int wid = tid >> 5;
    const int lane = tid & 31;
    const int g = lane >> 2;
    const int t = lane & 3;
    const int wm_i = wid >> 1;           // 0..1
    const int wn_i = wid & 1;            // 0..1

    const int mt = blockIdx.x >> 5;
    const int nt = blockIdx.x & 31;
    const int m0 = mt * BM;
    const int o0 = nt * BN;

    // ---- A cp.async addressing: 2048 chunks, 16 per thread ----
    const int arow = tid >> 4;           // 0..7, covers rows arow + 8j
    const int ac = tid & 15;             // chunk 0..15
    const __half* xsrc0 = g_xh + (size_t)(m0 + arow) * IN_F + ac * 8;
    const uint32_t adst0 = (uint32_t)(arow * 256 + ((ac ^ arow) << 4));

    // ---- WS cp.async addressing ----
    const int wkw = tid >> 5;            // kword 0..3
    const int wcg = tid & 31;            // col group 0..31

    float acc[4][8][4];
    #pragma unroll
    for (int mi = 0; mi < 4; ++mi)
        #pragma unroll
        for (int nj = 0; nj < 8; ++nj)
            #pragma unroll
            for (int r = 0; r < 4; ++r) acc[mi][nj][r] = 0.0f;

    // ---- ldmatrix A lane components ----
    const int a_row_l = wm_i * 64 + (lane & 15);
    const int a_hl = lane >> 4;
    const int colb = wn_i * 64 + g;      // B col base within tile
    const int t2 = 2 * t;

    auto fill_a = [&](int it, int s) {
        const uint32_t sb = smem_base + (uint32_t)(s * A_STAGE);
        const __half* src = xsrc0 + (size_t)it * BK;
        #pragma unroll
        for (int j = 0; j < 16; ++j)
            CP_ASYNC16(sb + adst0 + (uint32_t)(j * 2048),
                       (const char*)(src + (size_t)j * 8 * IN_F));
    };
    auto fill_ws = [&](int it, int s) {  // signs/scales of iteration `it`
        const uint32_t wb = smem_base + (uint32_t)(WS_BASE + s * WS_STAGE);
        const uint32_t* wsrc = g_packT + (size_t)(4 * it + wkw) * OUT_F + o0 + wcg * 4;
        CP_ASYNC16(wb + (uint32_t)(tid * 16), (const char*)wsrc);
        if (tid < 32) {
            const uint32_t* ssrc = g_ppT + (size_t)it * OUT_F + o0 + tid * 4;
            CP_ASYNC16(wb + 2048 + (uint32_t)(tid * 16), (const char*)ssrc);
        }
    };

    // ---- prologue: G0={A0,WS1}, G1={A1,WS2}; signs(0) via LDG ----
    fill_a(0, 0); fill_ws(1, 1); CP_COMMIT();
    fill_a(1, 1); fill_ws(2, 2); CP_COMMIT();

    uint32_t wc[4][8], ppc[8];
    #pragma unroll
    for (int nj = 0; nj < 8; ++nj) {
        const int c = o0 + colb + nj * 8;
        wc[0][nj] = __ldg(&g_packT[c]);
        wc[1][nj] = __ldg(&g_packT[(size_t)OUT_F + c]);
        wc[2][nj] = __ldg(&g_packT[(size_t)2 * OUT_F + c]);
        wc[3][nj] = __ldg(&g_packT[(size_t)3 * OUT_F + c]);
        ppc[nj]   = __ldg(&g_ppT[c]);
    }

    #pragma unroll 1
    for (int it = 0; it < KITERS; ++it) {
        // guarantee A(it) + WS(it+1) resident
        if (it < KITERS - 1) { CP_WAIT1(); } else { CP_WAIT0(); }
        __syncthreads();

        // commit G(it+2) = {A(it+2), WS(it+3)}
        if (it + 2 < KITERS) {
            fill_a(it + 2, (it + 2) % 3);
            if (it + 3 < KITERS) fill_ws(it + 3, (it + 3) % 3);
            CP_COMMIT();
        }

        // ---- compute from A stage it%3; signs already in regs ----
        const uint32_t abase = smem_base + (uint32_t)((it % 3) * A_STAGE);
        uint32_t af[2][4][4];
        #pragma unroll
        for (int mi = 0; mi < 4; ++mi) {
            const int r = a_row_l + mi * 16;
            const int ch = a_hl ^ (r & 7);
            ldsm_x4(af[0][mi], abase + (uint32_t)(r * 256 + (ch << 4)));
        }

        #pragma unroll
        for (int ks = 0; ks < 8; ++ks) {
            const int cur = ks & 1;
            if (ks < 7) {
                #pragma unroll
                for (int mi = 0; mi < 4; ++mi) {
                    const int r = a_row_l + mi * 16;
                    const int ch = (2 * (ks + 1) + a_hl) ^ (r & 7);
                    ldsm_x4(af[cur ^ 1][mi], abase + (uint32_t)(r * 256 + (ch << 4)));
                }
            }
            const int kw = ks >> 1;
            const int sh = t2 + ((ks & 1) << 4);
            #pragma unroll
            for (int nj = 0; nj < 8; ++nj) {
                uint32_t v = wc[kw][nj] >> sh;
                uint32_t b0 = ppc[nj] ^ (((v << 15) & 0x8000u) | ((v << 30) & 0x80000000u));
                uint32_t b1 = ppc[nj] ^ (((v << 7) & 0x8000u) | ((v << 22) & 0x80000000u));
                #pragma unroll
                for (int mi = 0; mi < 4; ++mi)
                    mma_fp16(acc[mi][nj], af[cur][mi], b0, b1);
            }
        }

        // ---- preload signs/scales(it+1) from WS ring (resident) ----
        if (it + 1 < KITERS) {
            const char* ws = smem + WS_BASE + ((it + 1) % 3) * WS_STAGE;
            const uint32_t* Wp = reinterpret_cast<const uint32_t*>(ws);
            const uint32_t* Sp = reinterpret_cast<const uint32_t*>(ws + 2048);
            #pragma unroll
            for (int nj = 0; nj < 8; ++nj) {
                const int c = colb + nj * 8;
                wc[0][nj] = Wp[c];
                wc[1][nj] = Wp[128 + c];
                wc[2][nj] = Wp[256 + c];
                wc[3][nj] = Wp[384 + c];
                ppc[nj]   = Sp[c];
            }
        }
    }

    // ---- epilogue: direct STG.64 ----
    #pragma unroll
    for (int mi = 0; mi < 4; ++mi) {
        const int row = m0 + wm_i * 64 + mi * 16 + g;
        #pragma unroll
        for (int nj = 0; nj < 8; ++nj) {
            const int col = o0 + wn_i * 64 + nj * 8 + 2 * t;
            float2 v0 = make_float2(acc[mi][nj][0], acc[mi][nj][1]);
            float2 v1 = make_float2(acc[mi][nj][2], acc[mi][nj][3]);
            *reinterpret_cast<float2*>(out + (size_t)row * OUT_F + col) = v0;
            *reinterpret_cast<float2*>(out + (size_t)(row + 8) * OUT_F + col) = v1;
        }
    }
}

// ============================================================
// launch
// ============================================================
extern "C" void kernel_launch(void* const* d_in, const int* in_sizes, int n_in,
                              void* d_out, int out_size) {
    const float* x      = (const float*)d_in[0];
    const float* sw     = (const float*)d_in[1];
    const float* scales = (const float*)d_in[2];
    float* out = (float*)d_out;

    cudaFuncSetAttribute(bitlinear_mma_kernel,
                         cudaFuncAttributeMaxDynamicSharedMemorySize, SM_TOTAL);

    convert_x_kernel<<<(M_TOT * (size_t)IN_F) / (8 * 256), 256>>>((const float4*)x);
    pack_signs_kernel<<<65536, 256>>>(sw);
    pack_scales_kernel<<<512, 256>>>(scales);

    // 64 M-tiles x 32 N-tiles
    bitlinear_mma_kernel<<<(M_TOT / BM) * (OUT_F / BN), NTH, SM_TOTAL>>>(out);
}

// round 11
// speedup vs baseline: 1.2115x; 1.0612x over previous
#include <cuda_runtime.h>
#include <cuda_fp16.h>
#include <cstdint>

// ---------------- problem constants ----------------
#define IN_F   4096
#define OUT_F  4096
#define M_TOT  8192
#define BK     128          // k per iteration (= one scale group, 256B rows)
#define KITERS (IN_F / BK)  // 32
#define BM     128
#define BN     128
#define NTH    128          // 4 warps: 2 (M) x 2 (N), 64x64 warp tiles

// ---------------- static device scratch ----------------
// inverted transposed sign bits: bit=1 -> weight NEGATIVE; [kword][o]
__device__ uint32_t g_packT[(size_t)(IN_F / 32) * OUT_F];   // 2 MB
__device__ __half   g_xh[(size_t)M_TOT * IN_F];             // 64 MB
// per (kgroup, o): half2(s, s) as uint32
__device__ uint32_t g_ppT[(size_t)(IN_F / 128) * OUT_F];    // 512 KB

// ---------------- SMEM stage layout (bytes) ----------------
// A: 32768 (128 rows x 256B, 16 chunks, xor-8 swizzle)
// W: 2048  (4 kwords x 128 cols x 4B)
// S: 512   (128 cols x 4B half2 scale)
#define STG_A      0
#define STG_W      32768
#define STG_S      34816
#define STG_STRIDE 35328
#define STAGES     3
#define SM_TOTAL   (STAGES * STG_STRIDE)   // 105984

// ---------------- helpers ----------------
static __device__ __forceinline__ uint32_t smem_u32(const void* p) {
    uint32_t a;
    asm("{ .reg .u64 t; cvta.to.shared.u64 t, %1; cvt.u32.u64 %0, t; }"
        : "=r"(a) : "l"(p));
    return a;
}

#define CP_ASYNC16(dst, src) \
    asm volatile("cp.async.cg.shared.global [%0], [%1], 16;" :: "r"(dst), "l"(src))
#define CP_COMMIT()  asm volatile("cp.async.commit_group;" ::: "memory")
#define CP_WAIT1()   asm volatile("cp.async.wait_group 1;" ::: "memory")

static __device__ __forceinline__ void ldsm_x4(uint32_t* r, uint32_t addr) {
    asm volatile("ldmatrix.sync.aligned.m8n8.x4.shared.b16 {%0,%1,%2,%3}, [%4];"
                 : "=r"(r[0]), "=r"(r[1]), "=r"(r[2]), "=r"(r[3]) : "r"(addr));
}

// NOTE: non-volatile on purpose — register-only semantics; lets ptxas pack
// HMMA bursts without honoring source-order interleave with b-build ALU.
static __device__ __forceinline__ void mma_fp16(float* d, const uint32_t* a,
                                                uint32_t b0, uint32_t b1) {
    asm("mma.sync.aligned.m16n8k16.row.col.f32.f16.f16.f32 "
        "{%0,%1,%2,%3}, {%4,%5,%6,%7}, {%8,%9}, {%0,%1,%2,%3};"
        : "+f"(d[0]), "+f"(d[1]), "+f"(d[2]), "+f"(d[3])
        : "r"(a[0]), "r"(a[1]), "r"(a[2]), "r"(a[3]), "r"(b0), "r"(b1));
}

// ============================================================
// Fused prep kernel, grid-sectioned:
//  blocks [0, 16384)        : X fp32 -> fp16 (8 floats / thread)
//  blocks [16384, 24576)    : pack inverted signs transposed (64 words / block)
//  blocks [24576, 25088)    : scales -> half2(s,s) transposed
// ============================================================
#define PREP_CONVERT_BLOCKS 16384
#define PREP_SIGN_BLOCKS    8192
#define PREP_SCALE_BLOCKS   512
#define PREP_GRID (PREP_CONVERT_BLOCKS + PREP_SIGN_BLOCKS + PREP_SCALE_BLOCKS)

__global__ void __launch_bounds__(256)
prep_kernel(const float4* __restrict__ x4,
            const float* __restrict__ sw,
            const float* __restrict__ scales) {
    const int b = blockIdx.x;
    const int tid = threadIdx.x;

    if (b < PREP_CONVERT_BLOCKS) {
        size_t i = (size_t)b * 256 + tid;        // 8 floats each
        float4 a = x4[2 * i];
        float4 c = x4[2 * i + 1];
        __half2 h0 = __floats2half2_rn(a.x, a.y);
        __half2 h1 = __floats2half2_rn(a.z, a.w);
        __half2 h2 = __floats2half2_rn(c.x, c.y);
        __half2 h3 = __floats2half2_rn(c.z, c.w);
        uint4 q;
        q.x = *reinterpret_cast<uint32_t*>(&h0);
        q.y = *reinterpret_cast<uint32_t*>(&h1);
        q.z = *reinterpret_cast<uint32_t*>(&h2);
        q.w = *reinterpret_cast<uint32_t*>(&h3);
        *reinterpret_cast<uint4*>(&g_xh[i * 8]) = q;
    } else if (b < PREP_CONVERT_BLOCKS + PREP_SIGN_BLOCKS) {
        const int bb = b - PREP_CONVERT_BLOCKS;
        const int wid = tid >> 5;
        const int lane = tid & 31;
        #pragma unroll
        for (int j = 0; j < 8; ++j) {
            uint32_t W = (uint32_t)bb * 64 + wid * 8 + j;   // word 0..524287
            uint32_t o = W >> 7;
            uint32_t kw = W & 127;
            float v = sw[(size_t)o * IN_F + kw * 32 + lane];
            uint32_t m = __ballot_sync(0xFFFFFFFFu, v < 0.0f);
            if (lane == 0) g_packT[(size_t)kw * OUT_F + o] = m;
        }
    } else {
        const int idx = (b - PREP_CONVERT_BLOCKS - PREP_SIGN_BLOCKS) * 256 + tid;
        const int kg = idx >> 12;
        const int o = idx & 4095;
        __half h = __float2half_rn(scales[(size_t)o * (IN_F / 128) + kg]);
        __half2 hh = __half2half2(h);
        g_ppT[(size_t)kg * OUT_F + o] = *reinterpret_cast<uint32_t*>(&hh);
    }
}

// ============================================================
// GEMM: fp16 mma.sync, CTA 128x128xBK128, 4 warps 64x64 (R6 base)
// ============================================================
__global__ void __launch_bounds__(NTH, 2)
bitlinear_mma_kernel(float* __restrict__ out) {
    extern __shared__ char smem[];
    const uint32_t smem_base = smem_u32(smem);

    const int tid = threadIdx.x;
    const int wid = tid >> 5;
    const int lane = tid & 31;
    const int g = lane >> 2;
    const int t = lane & 3;
    const int wm_i = wid >> 1;
    const int wn_i = wid & 1;

    const int mt = blockIdx.x >> 5;
    const int nt = blockIdx.x & 31;
    const int m0 = mt * BM;
    const int o0 = nt * BN;

    // ---- A cp.async addressing: 2048 chunks, 16 per thread ----
    const int arow = tid >> 4;           // 0..7, covers rows arow + 8j
    const int ac = tid & 15;             // chunk 0..15
    const __half* xsrc0 = g_xh + (size_t)(m0 + arow) * IN_F + ac * 8;
    const uint32_t adst0 = (uint32_t)(arow * 256 + ((ac ^ (arow & 7)) << 4));

    // ---- W/S cp.async addressing ----
    const int wkw = tid >> 5;            // kword 0..3
    const int wcg = tid & 31;            // col group

    float acc[4][8][4];
    #pragma unroll
    for (int mi = 0; mi < 4; ++mi)
        #pragma unroll
        for (int nj = 0; nj < 8; ++nj)
            #pragma unroll
            for (int r = 0; r < 4; ++r) acc[mi][nj][r] = 0.0f;

    // ---- ldmatrix A lane components ----
    const int a_row_l = wm_i * 64 + (lane & 15);
    const int a_hl = lane >> 4;          // 0/1 -> chunk 2ks + hl
    const int colb = wn_i * 64 + g;
    const int t2 = 2 * t;

    auto stage_fill = [&](int it, int s) {
        const uint32_t sb = smem_base + (uint32_t)(s * STG_STRIDE);
        const __half* src = xsrc0 + (size_t)it * BK;
        #pragma unroll
        for (int j = 0; j < 16; ++j)
            CP_ASYNC16(sb + adst0 + (uint32_t)(j * 2048),
                       (const char*)(src + (size_t)j * 8 * IN_F));
        {
            const uint32_t* wsrc = g_packT + (size_t)(4 * it + wkw) * OUT_F + o0 + wcg * 4;
            CP_ASYNC16(sb + STG_W + (uint32_t)(tid * 16), (const char*)wsrc);
        }
        if (tid < 32) {
            const uint32_t* ssrc = g_ppT + (size_t)it * OUT_F + o0 + tid * 4;
            CP_ASYNC16(sb + STG_S + (uint32_t)(tid * 16), (const char*)ssrc);
        }
    };

    stage_fill(0, 0);
    CP_COMMIT();

    int sa = 0;

    #pragma unroll 1
    for (int it = 0; it < KITERS; ++it) {
        if (it < KITERS - 1) {
            const int sn3 = (sa == 2) ? 0 : sa + 1;
            stage_fill(it + 1, sn3);
        }
        CP_COMMIT();
        CP_WAIT1();
        __syncthreads();

        const char* st = smem + sa * STG_STRIDE;
        const uint32_t abase = smem_base + (uint32_t)(sa * STG_STRIDE);

        // ---- sign words (4 kwords) + scale word for this lane's 8 cols ----
        uint32_t w[4][8], pp[8];
        {
            const uint32_t* Wp = reinterpret_cast<const uint32_t*>(st + STG_W);
            const uint32_t* Sp = reinterpret_cast<const uint32_t*>(st + STG_S);
            #pragma unroll
            for (int nj = 0; nj < 8; ++nj) {
                const int c = colb + nj * 8;
                w[0][nj] = Wp[c];
                w[1][nj] = Wp[128 + c];
                w[2][nj] = Wp[256 + c];
                w[3][nj] = Wp[384 + c];
                pp[nj] = Sp[c];
            }
        }

        // ---- software-pipelined A fragments across 8 ksteps ----
        uint32_t af[2][4][4];
        #pragma unroll
        for (int mi = 0; mi < 4; ++mi) {
            const int r = a_row_l + mi * 16;
            const int ch = a_hl ^ (r & 7);
            ldsm_x4(af[0][mi], abase + (uint32_t)(r * 256 + (ch << 4)));
        }

        #pragma unroll
        for (int ks = 0; ks < 8; ++ks) {
            const int cur = ks & 1;
            if (ks < 7) {
                #pragma unroll
                for (int mi = 0; mi < 4; ++mi) {
                    const int r = a_row_l + mi * 16;
                    const int ch = (2 * (ks + 1) + a_hl) ^ (r & 7);
                    ldsm_x4(af[cur ^ 1][mi], abase + (uint32_t)(r * 256 + (ch << 4)));
                }
            }
            const int kw = ks >> 1;
            const int sh = t2 + ((ks & 1) << 4);

            // precompute ALL B registers for this kstep, then MMA burst
            uint32_t b0r[8], b1r[8];
            #pragma unroll
            for (int nj = 0; nj < 8; ++nj) {
                uint32_t v = w[kw][nj] >> sh;
                b0r[nj] = pp[nj] ^ (((v << 15) & 0x8000u) | ((v << 30) & 0x80000000u));
                b1r[nj] = pp[nj] ^ (((v << 7) & 0x8000u) | ((v << 22) & 0x80000000u));
            }
            #pragma unroll
            for (int nj = 0; nj < 8; ++nj)
                #pragma unroll
                for (int mi = 0; mi < 4; ++mi)
                    mma_fp16(acc[mi][nj], af[cur][mi], b0r[nj], b1r[nj]);
        }

        sa = (sa == 2) ? 0 : sa + 1;
    }

    // ---- epilogue: direct STG.64 ----
    #pragma unroll
    for (int mi = 0; mi < 4; ++mi) {
        const int row = m0 + wm_i * 64 + mi * 16 + g;
        #pragma unroll
        for (int nj = 0; nj < 8; ++nj) {
            const int col = o0 + wn_i * 64 + nj * 8 + 2 * t;
            float2 v0 = make_float2(acc[mi][nj][0], acc[mi][nj][1]);
            float2 v1 = make_float2(acc[mi][nj][2], acc[mi][nj][3]);
            *reinterpret_cast<float2*>(out + (size_t)row * OUT_F + col) = v0;
            *reinterpret_cast<float2*>(out + (size_t)(row + 8) * OUT_F + col) = v1;
        }
    }
}

// ============================================================
// launch
// ============================================================
extern "C" void kernel_launch(void* const* d_in, const int* in_sizes, int n_in,
                              void* d_out, int out_size) {
    const float* x      = (const float*)d_in[0];
    const float* sw     = (const float*)d_in[1];
    const float* scales = (const float*)d_in[2];
    float* out = (float*)d_out;

    cudaFuncSetAttribute(bitlinear_mma_kernel,
                         cudaFuncAttributeMaxDynamicSharedMemorySize, SM_TOTAL);

    // fused prep: convert + pack signs + pack scales in one launch
    prep_kernel<<<PREP_GRID, 256>>>((const float4*)x, sw, scales);

    // GEMM: 64 M-tiles x 32 N-tiles
    bitlinear_mma_kernel<<<(M_TOT / BM) * (OUT_F / BN), NTH, SM_TOTAL>>>(out);
}

// round 12
// speedup vs baseline: 1.3447x; 1.1100x over previous
#include <cuda_runtime.h>
#include <cuda_fp16.h>
#include <cstdint>

// ---------------- problem constants ----------------
#define IN_F   4096
#define OUT_F  4096
#define M_TOT  8192
#define BK     128          // k per iteration (= one scale group, 256B rows)
#define KITERS (IN_F / BK)  // 32
#define BM     128
#define BN     128
#define NTH    128          // 4 warps: 2 (M) x 2 (N), 64x64 warp tiles

// ---------------- static device scratch ----------------
// Z-packed inverted sign words, transposed: g_packT[kw*4096 + o]
//   bit j      (j<16) = 1 iff weight(o, 32kw + 2j)   < 0
//   bit 16+j   (j<16) = 1 iff weight(o, 32kw + 2j+1) < 0
__device__ uint32_t g_packT[(size_t)(IN_F / 32) * OUT_F];   // 2 MB
__device__ __half   g_xh[(size_t)M_TOT * IN_F];             // 64 MB
// per (kgroup, o): half2(s, s) as uint32
__device__ uint32_t g_ppT[(size_t)(IN_F / 128) * OUT_F];    // 512 KB

// ---------------- SMEM stage layout (bytes) ----------------
#define STG_A      0
#define STG_W      32768
#define STG_S      34816
#define STG_STRIDE 35328
#define STAGES     3
#define SM_TOTAL   (STAGES * STG_STRIDE)   // 105984

// ---------------- helpers ----------------
static __device__ __forceinline__ uint32_t smem_u32(const void* p) {
    uint32_t a;
    asm("{ .reg .u64 t; cvta.to.shared.u64 t, %1; cvt.u32.u64 %0, t; }"
        : "=r"(a) : "l"(p));
    return a;
}

#define CP_ASYNC16(dst, src) \
    asm volatile("cp.async.cg.shared.global [%0], [%1], 16;" :: "r"(dst), "l"(src))
#define CP_COMMIT()  asm volatile("cp.async.commit_group;" ::: "memory")
#define CP_WAIT1()   asm volatile("cp.async.wait_group 1;" ::: "memory")

static __device__ __forceinline__ void ldsm_x4(uint32_t* r, uint32_t addr) {
    asm volatile("ldmatrix.sync.aligned.m8n8.x4.shared.b16 {%0,%1,%2,%3}, [%4];"
                 : "=r"(r[0]), "=r"(r[1]), "=r"(r[2]), "=r"(r[3]) : "r"(addr));
}

static __device__ __forceinline__ void mma_fp16(float* d, const uint32_t* a,
                                                uint32_t b0, uint32_t b1) {
    asm("mma.sync.aligned.m16n8k16.row.col.f32.f16.f16.f32 "
        "{%0,%1,%2,%3}, {%4,%5,%6,%7}, {%8,%9}, {%0,%1,%2,%3};"
        : "+f"(d[0]), "+f"(d[1]), "+f"(d[2]), "+f"(d[3])
        : "r"(a[0]), "r"(a[1]), "r"(a[2]), "r"(a[3]), "r"(b0), "r"(b1));
}

// ============================================================
// Fused prep kernel, grid-sectioned
// ============================================================
#define PREP_CONVERT_BLOCKS 16384
#define PREP_SIGN_BLOCKS    8192
#define PREP_SCALE_BLOCKS   512
#define PREP_GRID (PREP_CONVERT_BLOCKS + PREP_SIGN_BLOCKS + PREP_SCALE_BLOCKS)

__global__ void __launch_bounds__(256)
prep_kernel(const float4* __restrict__ x4,
            const float* __restrict__ sw,
            const float* __restrict__ scales) {
    const int b = blockIdx.x;
    const int tid = threadIdx.x;

    if (b < PREP_CONVERT_BLOCKS) {
        size_t i = (size_t)b * 256 + tid;        // 8 floats each
        float4 a = x4[2 * i];
        float4 c = x4[2 * i + 1];
        __half2 h0 = __floats2half2_rn(a.x, a.y);
        __half2 h1 = __floats2half2_rn(a.z, a.w);
        __half2 h2 = __floats2half2_rn(c.x, c.y);
        __half2 h3 = __floats2half2_rn(c.z, c.w);
        uint4 q;
        q.x = *reinterpret_cast<uint32_t*>(&h0);
        q.y = *reinterpret_cast<uint32_t*>(&h1);
        q.z = *reinterpret_cast<uint32_t*>(&h2);
        q.w = *reinterpret_cast<uint32_t*>(&h3);
        *reinterpret_cast<uint4*>(&g_xh[i * 8]) = q;
    } else if (b < PREP_CONVERT_BLOCKS + PREP_SIGN_BLOCKS) {
        const int bb = b - PREP_CONVERT_BLOCKS;
        const int wid = tid >> 5;
        const int lane = tid & 31;
        // Z-pack: lane L votes element e = 2L (L<16) or 2(L-16)+1 (L>=16)
        const int e = ((2 * lane) & 31) | (lane >> 4);
        #pragma unroll
        for (int j = 0; j < 8; ++j) {
            uint32_t W = (uint32_t)bb * 64 + wid * 8 + j;   // word 0..524287
            uint32_t o = W >> 7;
            uint32_t kw = W & 127;
            float v = sw[(size_t)o * IN_F + kw * 32 + e];
            uint32_t m = __ballot_sync(0xFFFFFFFFu, v < 0.0f);
            if (lane == 0) g_packT[(size_t)kw * OUT_F + o] = m;
        }
    } else {
        const int idx = (b - PREP_CONVERT_BLOCKS - PREP_SIGN_BLOCKS) * 256 + tid;
        const int kg = idx >> 12;
        const int o = idx & 4095;
        __half h = __float2half_rn(scales[(size_t)o * (IN_F / 128) + kg]);
        __half2 hh = __half2half2(h);
        g_ppT[(size_t)kg * OUT_F + o] = *reinterpret_cast<uint32_t*>(&hh);
    }
}

// ============================================================
// GEMM: fp16 mma.sync, CTA 128x128xBK128, 4 warps 64x64
// B built in regs: 1 funnel-rotate + 1 LOP3 per B register.
// ============================================================
__global__ void __launch_bounds__(NTH, 2)
bitlinear_mma_kernel(float* __restrict__ out) {
    extern __shared__ char smem[];
    const uint32_t smem_base = smem_u32(smem);

    const int tid = threadIdx.x;
    const int wid = tid >> 5;
    const int lane = tid & 31;
    const int g = lane >> 2;
    const int t = lane & 3;
    const int wm_i = wid >> 1;
    const int wn_i = wid & 1;

    const int mt = blockIdx.x >> 5;
    const int nt = blockIdx.x & 31;
    const int m0 = mt * BM;
    const int o0 = nt * BN;

    // ---- A cp.async addressing: 2048 chunks, 16 per thread ----
    const int arow = tid >> 4;           // 0..7, covers rows arow + 8j
    const int ac = tid & 15;             // chunk 0..15
    const __half* xsrc0 = g_xh + (size_t)(m0 + arow) * IN_F + ac * 8;
    const uint32_t adst0 = (uint32_t)(arow * 256 + ((ac ^ (arow & 7)) << 4));

    // ---- W/S cp.async addressing ----
    const int wkw = tid >> 5;            // kword 0..3
    const int wcg = tid & 31;            // col group

    float acc[4][8][4];
    #pragma unroll
    for (int mi = 0; mi < 4; ++mi)
        #pragma unroll
        for (int nj = 0; nj < 8; ++nj)
            #pragma unroll
            for (int r = 0; r < 4; ++r) acc[mi][nj][r] = 0.0f;

    // ---- ldmatrix A lane components ----
    const int a_row_l = wm_i * 64 + (lane & 15);
    const int a_hl = lane >> 4;          // 0/1 -> chunk 2ks + hl
    const int e7 = a_row_l & 7;          // swizzle row bits (mi-invariant)
    const int colb = wn_i * 64 + g;

    // rotate amounts (loop-invariant): bring Z bits (j, 16+j) to (15, 31)
    // b0: j = 8*(ks&1) + t ; b1: j = 8*(ks&1) + 4 + t ; amount = j + 17
    const uint32_t ra0e = (uint32_t)(t + 17);
    const uint32_t ra0o = (uint32_t)(t + 25);
    const uint32_t ra1e = (uint32_t)(t + 21);
    const uint32_t ra1o = (uint32_t)(t + 29);

    auto stage_fill = [&](int it, int s) {
        const uint32_t sb = smem_base + (uint32_t)(s * STG_STRIDE);
        const __half* src = xsrc0 + (size_t)it * BK;
        #pragma unroll
        for (int j = 0; j < 16; ++j)
            CP_ASYNC16(sb + adst0 + (uint32_t)(j * 2048),
                       (const char*)(src + (size_t)j * 8 * IN_F));
        {
            const uint32_t* wsrc = g_packT + (size_t)(4 * it + wkw) * OUT_F + o0 + wcg * 4;
            CP_ASYNC16(sb + STG_W + (uint32_t)(tid * 16), (const char*)wsrc);
        }
        if (tid < 32) {
            const uint32_t* ssrc = g_ppT + (size_t)it * OUT_F + o0 + tid * 4;
            CP_ASYNC16(sb + STG_S + (uint32_t)(tid * 16), (const char*)ssrc);
        }
    };

    stage_fill(0, 0);
    CP_COMMIT();

    int sa = 0;

    #pragma unroll 1
    for (int it = 0; it < KITERS; ++it) {
        if (it < KITERS - 1) {
            const int sn3 = (sa == 2) ? 0 : sa + 1;
            stage_fill(it + 1, sn3);
        }
        CP_COMMIT();
        CP_WAIT1();
        __syncthreads();

        const char* st = smem + sa * STG_STRIDE;
        const uint32_t abase = smem_base + (uint32_t)(sa * STG_STRIDE);

        // per-mi LDSM base addresses (row part)
        uint32_t abm[4];
        #pragma unroll
        for (int mi = 0; mi < 4; ++mi)
            abm[mi] = abase + (uint32_t)((a_row_l + mi * 16) * 256);

        // ---- Z words (4 kwords) + scale word for this lane's 8 cols ----
        uint32_t w[4][8], pp[8];
        {
            const uint32_t* Wp = reinterpret_cast<const uint32_t*>(st + STG_W);
            const uint32_t* Sp = reinterpret_cast<const uint32_t*>(st + STG_S);
            #pragma unroll
            for (int nj = 0; nj < 8; ++nj) {
                const int c = colb + nj * 8;
                w[0][nj] = Wp[c];
                w[1][nj] = Wp[128 + c];
                w[2][nj] = Wp[256 + c];
                w[3][nj] = Wp[384 + c];
                pp[nj] = Sp[c];
            }
        }

        // ---- software-pipelined A fragments across 8 ksteps ----
        uint32_t af[2][4][4];
        {
            const uint32_t off0 = (uint32_t)((a_hl ^ e7) << 4);
            #pragma unroll
            for (int mi = 0; mi < 4; ++mi)
                ldsm_x4(af[0][mi], abm[mi] + off0);
        }

        #pragma unroll
        for (int ks = 0; ks < 8; ++ks) {
            const int cur = ks & 1;
            if (ks < 7) {
                const uint32_t offn = (uint32_t)(((2 * (ks + 1) + a_hl) ^ e7) << 4);
                #pragma unroll
                for (int mi = 0; mi < 4; ++mi)
                    ldsm_x4(af[cur ^ 1][mi], abm[mi] + offn);
            }
            const int kw = ks >> 1;
            const uint32_t aE = (ks & 1) ? ra0o : ra0e;
            const uint32_t aO = (ks & 1) ? ra1o : ra1e;

            #pragma unroll
            for (int nj = 0; nj < 8; ++nj) {
                const uint32_t z = w[kw][nj];
                const uint32_t r0 = __funnelshift_r(z, z, aE);
                const uint32_t r1 = __funnelshift_r(z, z, aO);
                const uint32_t b0 = (r0 & 0x80008000u) ^ pp[nj];
                const uint32_t b1 = (r1 & 0x80008000u) ^ pp[nj];
                #pragma unroll
                for (int mi = 0; mi < 4; ++mi)
                    mma_fp16(acc[mi][nj], af[cur][mi], b0, b1);
            }
        }

        sa = (sa == 2) ? 0 : sa + 1;
    }

    // ---- epilogue: direct STG.64 ----
    #pragma unroll
    for (int mi = 0; mi < 4; ++mi) {
        const int row = m0 + wm_i * 64 + mi * 16 + g;
        #pragma unroll
        for (int nj = 0; nj < 8; ++nj) {
            const int col = o0 + wn_i * 64 + nj * 8 + 2 * t;
            float2 v0 = make_float2(acc[mi][nj][0], acc[mi][nj][1]);
            float2 v1 = make_float2(acc[mi][nj][2], acc[mi][nj][3]);
            *reinterpret_cast<float2*>(out + (size_t)row * OUT_F + col) = v0;
            *reinterpret_cast<float2*>(out + (size_t)(row + 8) * OUT_F + col) = v1;
        }
    }
}

// ============================================================
// launch
// ============================================================
extern "C" void kernel_launch(void* const* d_in, const int* in_sizes, int n_in,
                              void* d_out, int out_size) {
    const float* x      = (const float*)d_in[0];
    const float* sw     = (const float*)d_in[1];
    const float* scales = (const float*)d_in[2];
    float* out = (float*)d_out;

    cudaFuncSetAttribute(bitlinear_mma_kernel,
                         cudaFuncAttributeMaxDynamicSharedMemorySize, SM_TOTAL);

    prep_kernel<<<PREP_GRID, 256>>>((const float4*)x, sw, scales);

    // 64 M-tiles x 32 N-tiles
    bitlinear_mma_kernel<<<(M_TOT / BM) * (OUT_F / BN), NTH, SM_TOTAL>>>(out);
}

// round 13
// speedup vs baseline: 1.4123x; 1.0503x over previous
#include <cuda_runtime.h>
#include <cuda_fp16.h>
#include <cstdint>

// ---------------- problem constants ----------------
#define IN_F   4096
#define OUT_F  4096
#define M_TOT  8192
#define BK     128          // k per iteration (= one scale group, 256B rows)
#define KITERS (IN_F / BK)  // 32
#define BM     128
#define BN     128
#define NTH    128          // 4 warps, each M128 x N32

// ---------------- static device scratch ----------------
// Z-packed inverted sign words, transposed: g_packT[kw*4096 + o]
//   bit j      (j<16) = 1 iff weight(o, 32kw + 2j)   < 0
//   bit 16+j   (j<16) = 1 iff weight(o, 32kw + 2j+1) < 0
__device__ uint32_t g_packT[(size_t)(IN_F / 32) * OUT_F];   // 2 MB
__device__ __half   g_xh[(size_t)M_TOT * IN_F];             // 64 MB
// per (kgroup, o): half2(s, s) as uint32
__device__ uint32_t g_ppT[(size_t)(IN_F / 128) * OUT_F];    // 512 KB

// ---------------- SMEM stage layout (bytes) ----------------
#define STG_A      0
#define STG_W      32768
#define STG_S      34816
#define STG_STRIDE 35328
#define STAGES     3
#define SM_TOTAL   (STAGES * STG_STRIDE)   // 105984

// ---------------- helpers ----------------
static __device__ __forceinline__ uint32_t smem_u32(const void* p) {
    uint32_t a;
    asm("{ .reg .u64 t; cvta.to.shared.u64 t, %1; cvt.u32.u64 %0, t; }"
        : "=r"(a) : "l"(p));
    return a;
}

#define CP_ASYNC16(dst, src) \
    asm volatile("cp.async.cg.shared.global [%0], [%1], 16;" :: "r"(dst), "l"(src))
#define CP_COMMIT()  asm volatile("cp.async.commit_group;" ::: "memory")
#define CP_WAIT1()   asm volatile("cp.async.wait_group 1;" ::: "memory")

static __device__ __forceinline__ void ldsm_x4(uint32_t* r, uint32_t addr) {
    asm volatile("ldmatrix.sync.aligned.m8n8.x4.shared.b16 {%0,%1,%2,%3}, [%4];"
                 : "=r"(r[0]), "=r"(r[1]), "=r"(r[2]), "=r"(r[3]) : "r"(addr));
}

static __device__ __forceinline__ void mma_fp16(float* d, const uint32_t* a,
                                                uint32_t b0, uint32_t b1) {
    asm("mma.sync.aligned.m16n8k16.row.col.f32.f16.f16.f32 "
        "{%0,%1,%2,%3}, {%4,%5,%6,%7}, {%8,%9}, {%0,%1,%2,%3};"
        : "+f"(d[0]), "+f"(d[1]), "+f"(d[2]), "+f"(d[3])
        : "r"(a[0]), "r"(a[1]), "r"(a[2]), "r"(a[3]), "r"(b0), "r"(b1));
}

// ============================================================
// Fused prep kernel, grid-sectioned
// ============================================================
#define PREP_CONVERT_BLOCKS 16384
#define PREP_SIGN_BLOCKS    8192
#define PREP_SCALE_BLOCKS   512
#define PREP_GRID (PREP_CONVERT_BLOCKS + PREP_SIGN_BLOCKS + PREP_SCALE_BLOCKS)

__global__ void __launch_bounds__(256)
prep_kernel(const float4* __restrict__ x4,
            const float* __restrict__ sw,
            const float* __restrict__ scales) {
    const int b = blockIdx.x;
    const int tid = threadIdx.x;

    if (b < PREP_CONVERT_BLOCKS) {
        size_t i = (size_t)b * 256 + tid;        // 8 floats each
        float4 a = x4[2 * i];
        float4 c = x4[2 * i + 1];
        __half2 h0 = __floats2half2_rn(a.x, a.y);
        __half2 h1 = __floats2half2_rn(a.z, a.w);
        __half2 h2 = __floats2half2_rn(c.x, c.y);
        __half2 h3 = __floats2half2_rn(c.z, c.w);
        uint4 q;
        q.x = *reinterpret_cast<uint32_t*>(&h0);
        q.y = *reinterpret_cast<uint32_t*>(&h1);
        q.z = *reinterpret_cast<uint32_t*>(&h2);
        q.w = *reinterpret_cast<uint32_t*>(&h3);
        *reinterpret_cast<uint4*>(&g_xh[i * 8]) = q;
    } else if (b < PREP_CONVERT_BLOCKS + PREP_SIGN_BLOCKS) {
        const int bb = b - PREP_CONVERT_BLOCKS;
        const int wid = tid >> 5;
        const int lane = tid & 31;
        // Z-pack: lane L votes element e = 2L (L<16) or 2(L-16)+1 (L>=16)
        const int e = ((2 * lane) & 31) | (lane >> 4);
        #pragma unroll
        for (int j = 0; j < 8; ++j) {
            uint32_t W = (uint32_t)bb * 64 + wid * 8 + j;   // word 0..524287
            uint32_t o = W >> 7;
            uint32_t kw = W & 127;
            float v = sw[(size_t)o * IN_F + kw * 32 + e];
            uint32_t m = __ballot_sync(0xFFFFFFFFu, v < 0.0f);
            if (lane == 0) g_packT[(size_t)kw * OUT_F + o] = m;
        }
    } else {
        const int idx = (b - PREP_CONVERT_BLOCKS - PREP_SIGN_BLOCKS) * 256 + tid;
        const int kg = idx >> 12;
        const int o = idx & 4095;
        __half h = __float2half_rn(scales[(size_t)o * (IN_F / 128) + kg]);
        __half2 hh = __half2half2(h);
        g_ppT[(size_t)kg * OUT_F + o] = *reinterpret_cast<uint32_t*>(&hh);
    }
}

// ============================================================
// GEMM: fp16 mma.sync, CTA 128x128xBK128
// 4 warps, each M128 x N32: every B register feeds 8 MMAs.
// B built in regs: 1 funnel-rotate + 1 LOP3 per B register.
// ============================================================
__global__ void __launch_bounds__(NTH, 2)
bitlinear_mma_kernel(float* __restrict__ out) {
    extern __shared__ char smem[];
    const uint32_t smem_base = smem_u32(smem);

    const int tid = threadIdx.x;
    const int wid = tid >> 5;            // warp -> N slice
    const int lane = tid & 31;
    const int g = lane >> 2;
    const int t = lane & 3;

    const int mt = blockIdx.x >> 5;
    const int nt = blockIdx.x & 31;
    const int m0 = mt * BM;
    const int o0 = nt * BN;

    // ---- A cp.async addressing: 2048 chunks, 16 per thread ----
    const int arow = tid >> 4;           // 0..7, covers rows arow + 8j
    const int ac = tid & 15;             // chunk 0..15
    const __half* xsrc0 = g_xh + (size_t)(m0 + arow) * IN_F + ac * 8;
    const uint32_t adst0 = (uint32_t)(arow * 256 + ((ac ^ (arow & 7)) << 4));

    // ---- W/S cp.async addressing ----
    const int wkw = tid >> 5;            // kword 0..3
    const int wcg = tid & 31;            // col group

    float acc[8][4][4];
    #pragma unroll
    for (int mi = 0; mi < 8; ++mi)
        #pragma unroll
        for (int nj = 0; nj < 4; ++nj)
            #pragma unroll
            for (int r = 0; r < 4; ++r) acc[mi][nj][r] = 0.0f;

    // ---- ldmatrix A lane components ----
    const int a_row_l = lane & 15;       // + 16*mi, mi 0..7
    const int a_hl = lane >> 4;          // 0/1 -> chunk 2ks + hl
    const int e7 = a_row_l & 7;          // swizzle bits (mi-invariant)
    const int colb = wid * 32 + g;       // this warp's B col base

    // rotate amounts (loop-invariant): bring Z bits (j, 16+j) to (15, 31)
    const uint32_t ra0e = (uint32_t)(t + 17);
    const uint32_t ra0o = (uint32_t)(t + 25);
    const uint32_t ra1e = (uint32_t)(t + 21);
    const uint32_t ra1o = (uint32_t)(t + 29);

    auto stage_fill = [&](int it, int s) {
        const uint32_t sb = smem_base + (uint32_t)(s * STG_STRIDE);
        const __half* src = xsrc0 + (size_t)it * BK;
        #pragma unroll
        for (int j = 0; j < 16; ++j)
            CP_ASYNC16(sb + adst0 + (uint32_t)(j * 2048),
                       (const char*)(src + (size_t)j * 8 * IN_F));
        {
            const uint32_t* wsrc = g_packT + (size_t)(4 * it + wkw) * OUT_F + o0 + wcg * 4;
            CP_ASYNC16(sb + STG_W + (uint32_t)(tid * 16), (const char*)wsrc);
        }
        if (tid < 32) {
            const uint32_t* ssrc = g_ppT + (size_t)it * OUT_F + o0 + tid * 4;
            CP_ASYNC16(sb + STG_S + (uint32_t)(tid * 16), (const char*)ssrc);
        }
    };

    stage_fill(0, 0);
    CP_COMMIT();

    int sa = 0;

    #pragma unroll 1
    for (int it = 0; it < KITERS; ++it) {
        if (it < KITERS - 1) {
            const int sn3 = (sa == 2) ? 0 : sa + 1;
            stage_fill(it + 1, sn3);
        }
        CP_COMMIT();
        CP_WAIT1();
        __syncthreads();

        const char* st = smem + sa * STG_STRIDE;
        const uint32_t abase = smem_base + (uint32_t)(sa * STG_STRIDE)
                             + (uint32_t)(a_row_l * 256);

        // ---- Z words (4 kwords) + scale word for this lane's 4 cols ----
        uint32_t w[4][4], pp[4];
        {
            const uint32_t* Wp = reinterpret_cast<const uint32_t*>(st + STG_W);
            const uint32_t* Sp = reinterpret_cast<const uint32_t*>(st + STG_S);
            #pragma unroll
            for (int nj = 0; nj < 4; ++nj) {
                const int c = colb + nj * 8;
                w[0][nj] = Wp[c];
                w[1][nj] = Wp[128 + c];
                w[2][nj] = Wp[256 + c];
                w[3][nj] = Wp[384 + c];
                pp[nj] = Sp[c];
            }
        }

        // ---- software-pipelined A fragments across 8 ksteps ----
        uint32_t af[2][8][4];
        {
            const uint32_t off0 = (uint32_t)((a_hl ^ e7) << 4);
            #pragma unroll
            for (int mi = 0; mi < 8; ++mi)
                ldsm_x4(af[0][mi], abase + (uint32_t)(mi * 4096) + off0);
        }

        #pragma unroll
        for (int ks = 0; ks < 8; ++ks) {
            const int cur = ks & 1;
            if (ks < 7) {
                const uint32_t offn = (uint32_t)(((2 * (ks + 1) + a_hl) ^ e7) << 4);
                #pragma unroll
                for (int mi = 0; mi < 8; ++mi)
                    ldsm_x4(af[cur ^ 1][mi], abase + (uint32_t)(mi * 4096) + offn);
            }
            const int kw = ks >> 1;
            const uint32_t aE = (ks & 1) ? ra0o : ra0e;
            const uint32_t aO = (ks & 1) ? ra1o : ra1e;

            #pragma unroll
            for (int nj = 0; nj < 4; ++nj) {
                const uint32_t z = w[kw][nj];
                const uint32_t r0 = __funnelshift_r(z, z, aE);
                const uint32_t r1 = __funnelshift_r(z, z, aO);
                const uint32_t b0 = (r0 & 0x80008000u) ^ pp[nj];
                const uint32_t b1 = (r1 & 0x80008000u) ^ pp[nj];
                #pragma unroll
                for (int mi = 0; mi < 8; ++mi)
                    mma_fp16(acc[mi][nj], af[cur][mi], b0, b1);
            }
        }

        sa = (sa == 2) ? 0 : sa + 1;
    }

    // ---- epilogue: direct STG.64 ----
    #pragma unroll
    for (int mi = 0; mi < 8; ++mi) {
        const int row = m0 + mi * 16 + g;
        #pragma unroll
        for (int nj = 0; nj < 4; ++nj) {
            const int col = o0 + wid * 32 + nj * 8 + 2 * t;
            float2 v0 = make_float2(acc[mi][nj][0], acc[mi][nj][1]);
            float2 v1 = make_float2(acc[mi][nj][2], acc[mi][nj][3]);
            *reinterpret_cast<float2*>(out + (size_t)row * OUT_F + col) = v0;
            *reinterpret_cast<float2*>(out + (size_t)(row + 8) * OUT_F + col) = v1;
        }
    }
}

// ============================================================
// launch
// ============================================================
extern "C" void kernel_launch(void* const* d_in, const int* in_sizes, int n_in,
                              void* d_out, int out_size) {
    const float* x      = (const float*)d_in[0];
    const float* sw     = (const float*)d_in[1];
    const float* scales = (const float*)d_in[2];
    float* out = (float*)d_out;

    cudaFuncSetAttribute(bitlinear_mma_kernel,
                         cudaFuncAttributeMaxDynamicSharedMemorySize, SM_TOTAL);

    prep_kernel<<<PREP_GRID, 256>>>((const float4*)x, sw, scales);

    // 64 M-tiles x 32 N-tiles
    bitlinear_mma_kernel<<<(M_TOT / BM) * (OUT_F / BN), NTH, SM_TOTAL>>>(out);
}